// round 10
// baseline (speedup 1.0000x reference)
#include <cuda_runtime.h>

#define N_NODES 100000
#define N_EDGES 1600000
#define IN_F 128
#define HID_F 64
#define CLS_F 32
#define NBLK 391   // ceil(N_NODES/256)

// ---------------- scratch (16B-aligned for vector access) ------------------
__device__ __align__(16) float gv56_xws[N_NODES * HID_F];  // dinv[v]*(x@W1)[v]
__device__ __align__(16) float gv56_hw2s[N_NODES * CLS_F]; // dinv[v]*(h@W2)[v]
__device__ __align__(16) float gv56_dinv[N_NODES];
__device__ int   gv56_cnt[N_NODES];
__device__ int   gv56_rowptr[N_NODES + 1];
__device__ int   gv56_cursor[N_NODES];
__device__ int   gv56_col[N_EDGES];
__device__ int   gv56_bsum[512];
__device__ int   gv56_is64;

// ---------------- f32x2 helpers ---------------------------------------------
__device__ __forceinline__ unsigned long long pack2(float lo, float hi) {
    unsigned long long r;
    asm("mov.b64 %0, {%1, %2};" : "=l"(r) : "f"(lo), "f"(hi));
    return r;
}
__device__ __forceinline__ void unpack2(unsigned long long v, float& lo, float& hi) {
    asm("mov.b64 {%0, %1}, %2;" : "=f"(lo), "=f"(hi) : "l"(v));
}
#define FMA2(d, a, b, c) \
    asm("fma.rn.f32x2 %0, %1, %2, %3;" : "=l"(d) : "l"(a), "l"(b), "l"(c))

// ---------------- init: zero cnt + detect edge dtype ------------------------
__global__ __launch_bounds__(256) void k_init(const void* __restrict__ ei) {
    if (blockIdx.x == NBLK) {
        if (threadIdx.x < 32) {
            const long long* p = (const long long*)ei;
            long long v0 = p[threadIdx.x];
            long long v1 = p[threadIdx.x + 32];
            int bad = (v0 < 0) | (v0 >= (long long)N_NODES) |
                      (v1 < 0) | (v1 >= (long long)N_NODES);
            unsigned m = __ballot_sync(0xffffffffu, bad);
            if (threadIdx.x == 0) gv56_is64 = (m == 0u);
        }
        return;
    }
    int v = blockIdx.x * 256 + threadIdx.x;
    if (v < N_NODES) gv56_cnt[v] = 0;
}

__device__ __forceinline__ int edge_at(const void* __restrict__ ei, long long idx) {
    if (gv56_is64) return (int)((const long long*)ei)[idx];
    return ((const int*)ei)[idx];
}

// ---------------- CSR build --------------------------------------------------
__global__ __launch_bounds__(256) void k_count(const void* __restrict__ ei) {
    int e = blockIdx.x * 256 + threadIdx.x;
    if (e < N_EDGES) {
        int d = edge_at(ei, (long long)N_EDGES + e);
        if ((unsigned)d < (unsigned)N_NODES) atomicAdd(&gv56_cnt[d], 1);
    }
}

__global__ __launch_bounds__(256) void k_bsum() {
    __shared__ int red[8];
    int i = blockIdx.x * 256 + threadIdx.x;
    int v = (i < N_NODES) ? gv56_cnt[i] : 0;
#pragma unroll
    for (int o = 16; o; o >>= 1) v += __shfl_down_sync(0xffffffffu, v, o);
    if ((threadIdx.x & 31) == 0) red[threadIdx.x >> 5] = v;
    __syncthreads();
    if (threadIdx.x < 8) {
        int s = red[threadIdx.x];
#pragma unroll
        for (int o = 4; o; o >>= 1) s += __shfl_down_sync(0xffu, s, o);
        if (threadIdx.x == 0) gv56_bsum[blockIdx.x] = s;
    }
}

// per-block scan; block offset computed in-kernel from bsum
__global__ __launch_bounds__(256) void k_scan3() {
    __shared__ int s[256];
    __shared__ int red[8];
    const int t = threadIdx.x;

    int part = 0;
    for (int j = t; j < blockIdx.x; j += 256) part += gv56_bsum[j];
#pragma unroll
    for (int o = 16; o; o >>= 1) part += __shfl_down_sync(0xffffffffu, part, o);
    if ((t & 31) == 0) red[t >> 5] = part;
    __syncthreads();
    if (t < 8) {
        int sr = red[t];
#pragma unroll
        for (int o = 4; o; o >>= 1) sr += __shfl_down_sync(0xffu, sr, o);
        if (t == 0) red[0] = sr;
    }
    __syncthreads();
    const int off = red[0];

    int i = blockIdx.x * 256 + t;
    int v = (i < N_NODES) ? gv56_cnt[i] : 0;
    s[t] = v;
    __syncthreads();
    for (int o = 1; o < 256; o <<= 1) {
        int a = 0;
        if (t >= o) a = s[t - o];
        __syncthreads();
        s[t] += a;
        __syncthreads();
    }
    if (i < N_NODES) {
        int r = off + s[t] - v;
        gv56_rowptr[i] = r;
        gv56_cursor[i] = r;
        gv56_dinv[i] = rsqrtf((float)(v + 1));
        if (i == N_NODES - 1) gv56_rowptr[N_NODES] = r + v;
    }
}

__global__ __launch_bounds__(256) void k_fill(const void* __restrict__ ei) {
    int e = blockIdx.x * 256 + threadIdx.x;
    if (e < N_EDGES) {
        int s = edge_at(ei, e);
        int d = edge_at(ei, (long long)N_EDGES + e);
        if ((unsigned)d < (unsigned)N_NODES && (unsigned)s < (unsigned)N_NODES) {
            int slot = atomicAdd(&gv56_cursor[d], 1);
            gv56_col[slot] = s;
        }
    }
}

// ---------------- GEMM1: xws = dinv * (X @ W1), f32x2 math ------------------
// 128 rows x 64 cols per block, 256 threads, thread tile 4 rows x 8 cols.
// X k-chunk (16) staged transposed so a = LDS.128; w = 2x LDS.128.
__global__ __launch_bounds__(256) void k_gemm1(const float* __restrict__ X,
                                               const float* __restrict__ W) {
    __shared__ __align__(16) float sW[IN_F * HID_F];   // 32 KB
    __shared__ __align__(16) float sXT[16 * 132];      // 8.4 KB transposed chunk

    const int tid = threadIdx.x;
    const int tx = tid & 7;    // col group: cols tx*8 .. +7
    const int ty = tid >> 3;   // row group: rows ty*4 .. +3 (0..31)
    const int m0 = blockIdx.x * 128;

    for (int i = tid; i < IN_F * HID_F / 4; i += 256)
        ((float4*)sW)[i] = ((const float4*)W)[i];

    // acc[i][j]: f32x2 over (row ty*4+i, cols tx*8+2j .. +1)
    unsigned long long acc[4][4];
#pragma unroll
    for (int i = 0; i < 4; i++)
#pragma unroll
        for (int j = 0; j < 4; j++) acc[i][j] = 0ull;

    for (int kt = 0; kt < IN_F; kt += 16) {
        __syncthreads();
        // stage 128 rows x 16 k transposed: 512 float4, 2 per thread
#pragma unroll
        for (int idx = tid; idx < 512; idx += 256) {
            int r = idx & 127, c4 = idx >> 7;   // c4 in 0..3
            int gr = m0 + r;
            float4 v = make_float4(0.f, 0.f, 0.f, 0.f);
            if (gr < N_NODES)
                v = *(const float4*)&X[(size_t)gr * IN_F + kt + c4 * 4];
            sXT[(c4 * 4 + 0) * 132 + r] = v.x;
            sXT[(c4 * 4 + 1) * 132 + r] = v.y;
            sXT[(c4 * 4 + 2) * 132 + r] = v.z;
            sXT[(c4 * 4 + 3) * 132 + r] = v.w;
        }
        __syncthreads();

#pragma unroll
        for (int kk = 0; kk < 16; kk++) {
            float4 a4 = *(const float4*)&sXT[kk * 132 + ty * 4];
            float4 w0 = *(const float4*)&sW[(kt + kk) * HID_F + tx * 8];
            float4 w1 = *(const float4*)&sW[(kt + kk) * HID_F + tx * 8 + 4];
            unsigned long long wp0 = pack2(w0.x, w0.y);
            unsigned long long wp1 = pack2(w0.z, w0.w);
            unsigned long long wp2 = pack2(w1.x, w1.y);
            unsigned long long wp3 = pack2(w1.z, w1.w);
            unsigned long long ap0 = pack2(a4.x, a4.x);
            unsigned long long ap1 = pack2(a4.y, a4.y);
            unsigned long long ap2 = pack2(a4.z, a4.z);
            unsigned long long ap3 = pack2(a4.w, a4.w);
            FMA2(acc[0][0], ap0, wp0, acc[0][0]);
            FMA2(acc[0][1], ap0, wp1, acc[0][1]);
            FMA2(acc[0][2], ap0, wp2, acc[0][2]);
            FMA2(acc[0][3], ap0, wp3, acc[0][3]);
            FMA2(acc[1][0], ap1, wp0, acc[1][0]);
            FMA2(acc[1][1], ap1, wp1, acc[1][1]);
            FMA2(acc[1][2], ap1, wp2, acc[1][2]);
            FMA2(acc[1][3], ap1, wp3, acc[1][3]);
            FMA2(acc[2][0], ap2, wp0, acc[2][0]);
            FMA2(acc[2][1], ap2, wp1, acc[2][1]);
            FMA2(acc[2][2], ap2, wp2, acc[2][2]);
            FMA2(acc[2][3], ap2, wp3, acc[2][3]);
            FMA2(acc[3][0], ap3, wp0, acc[3][0]);
            FMA2(acc[3][1], ap3, wp1, acc[3][1]);
            FMA2(acc[3][2], ap3, wp2, acc[3][2]);
            FMA2(acc[3][3], ap3, wp3, acc[3][3]);
        }
    }

#pragma unroll
    for (int i = 0; i < 4; i++) {
        int gr = m0 + ty * 4 + i;
        if (gr < N_NODES) {
            float dv = gv56_dinv[gr];
            float4 o0, o1;
            unpack2(acc[i][0], o0.x, o0.y);
            unpack2(acc[i][1], o0.z, o0.w);
            unpack2(acc[i][2], o1.x, o1.y);
            unpack2(acc[i][3], o1.z, o1.w);
            o0.x *= dv; o0.y *= dv; o0.z *= dv; o0.w *= dv;
            o1.x *= dv; o1.y *= dv; o1.z *= dv; o1.w *= dv;
            *(float4*)&gv56_xws[(size_t)gr * HID_F + tx * 8]     = o0;
            *(float4*)&gv56_xws[(size_t)gr * HID_F + tx * 8 + 4] = o1;
        }
    }
}

// ---------------- fused prop1 + ReLU + GEMM2 (pre-scaled inputs) ------------
__global__ __launch_bounds__(256) void k_prop1g2(const float* __restrict__ b1,
                                                 const float* __restrict__ W2) {
    __shared__ __align__(16) float sh[8][HID_F];
    const int warp = threadIdx.x >> 5;
    const int lane = threadIdx.x & 31;
    const int v = blockIdx.x * 8 + warp;
    if (v >= N_NODES) return;

    const float2* __restrict__ xw2 = (const float2*)gv56_xws;
    float dv = gv56_dinv[v];
    float2 self = xw2[(size_t)v * 32 + lane];
    float ax = self.x;
    float ay = self.y;

    int p = gv56_rowptr[v];
    const int e = gv56_rowptr[v + 1];
    for (; p + 8 <= e; p += 8) {
        int u0 = gv56_col[p],     u1 = gv56_col[p + 1];
        int u2 = gv56_col[p + 2], u3 = gv56_col[p + 3];
        int u4 = gv56_col[p + 4], u5 = gv56_col[p + 5];
        int u6 = gv56_col[p + 6], u7 = gv56_col[p + 7];
        float2 f0 = xw2[(size_t)u0 * 32 + lane];
        float2 f1 = xw2[(size_t)u1 * 32 + lane];
        float2 f2 = xw2[(size_t)u2 * 32 + lane];
        float2 f3 = xw2[(size_t)u3 * 32 + lane];
        float2 f4 = xw2[(size_t)u4 * 32 + lane];
        float2 f5 = xw2[(size_t)u5 * 32 + lane];
        float2 f6 = xw2[(size_t)u6 * 32 + lane];
        float2 f7 = xw2[(size_t)u7 * 32 + lane];
        ax += f0.x + f1.x + f2.x + f3.x + f4.x + f5.x + f6.x + f7.x;
        ay += f0.y + f1.y + f2.y + f3.y + f4.y + f5.y + f6.y + f7.y;
    }
    for (; p < e; p++) {
        int u = gv56_col[p];
        float2 f = xw2[(size_t)u * 32 + lane];
        ax += f.x;
        ay += f.y;
    }

    float2 bb = ((const float2*)b1)[lane];
    sh[warp][2 * lane]     = fmaxf(fmaf(ax, dv, bb.x), 0.0f);
    sh[warp][2 * lane + 1] = fmaxf(fmaf(ay, dv, bb.y), 0.0f);
    __syncwarp();

    float o = 0.0f;
#pragma unroll 8
    for (int k = 0; k < HID_F; k++)
        o = fmaf(sh[warp][k], W2[k * CLS_F + lane], o);
    gv56_hw2s[(size_t)v * CLS_F + lane] = o * dv;
}

// ---------------- prop2 -------------------------------------------------------
__global__ __launch_bounds__(256) void k_prop2(const float* __restrict__ b2,
                                               float* __restrict__ out) {
    const int warp = threadIdx.x >> 5;
    const int lane = threadIdx.x & 31;
    const int v = blockIdx.x * 8 + warp;
    if (v >= N_NODES) return;

    float dv = gv56_dinv[v];
    float acc = gv56_hw2s[(size_t)v * CLS_F + lane];

    int p = gv56_rowptr[v];
    const int e = gv56_rowptr[v + 1];
    for (; p + 8 <= e; p += 8) {
        int u0 = gv56_col[p],     u1 = gv56_col[p + 1];
        int u2 = gv56_col[p + 2], u3 = gv56_col[p + 3];
        int u4 = gv56_col[p + 4], u5 = gv56_col[p + 5];
        int u6 = gv56_col[p + 6], u7 = gv56_col[p + 7];
        float f0 = gv56_hw2s[(size_t)u0 * CLS_F + lane];
        float f1 = gv56_hw2s[(size_t)u1 * CLS_F + lane];
        float f2 = gv56_hw2s[(size_t)u2 * CLS_F + lane];
        float f3 = gv56_hw2s[(size_t)u3 * CLS_F + lane];
        float f4 = gv56_hw2s[(size_t)u4 * CLS_F + lane];
        float f5 = gv56_hw2s[(size_t)u5 * CLS_F + lane];
        float f6 = gv56_hw2s[(size_t)u6 * CLS_F + lane];
        float f7 = gv56_hw2s[(size_t)u7 * CLS_F + lane];
        acc += f0 + f1 + f2 + f3 + f4 + f5 + f6 + f7;
    }
    for (; p < e; p++) {
        int u = gv56_col[p];
        acc += gv56_hw2s[(size_t)u * CLS_F + lane];
    }
    out[(size_t)v * CLS_F + lane] = fmaf(acc, dv, b2[lane]);
}

// ---------------- launch ------------------------------------------------------
extern "C" void kernel_launch(void* const* d_in, const int* in_sizes, int n_in,
                              void* d_out, int out_size) {
    const float* x  = nullptr;
    const void*  ei = nullptr;
    const float* W1 = nullptr;
    const float* b1 = nullptr;
    const float* W2 = nullptr;
    const float* b2 = nullptr;

    for (int i = 0; i < n_in; i++) {
        switch (in_sizes[i]) {
            case N_NODES * IN_F:  x  = (const float*)d_in[i]; break;
            case 2 * N_EDGES:     ei = d_in[i];               break;
            case N_EDGES:         /* edge_attr unused */       break;
            case IN_F * HID_F:    W1 = (const float*)d_in[i]; break;
            case HID_F:           b1 = (const float*)d_in[i]; break;
            case HID_F * CLS_F:   W2 = (const float*)d_in[i]; break;
            case CLS_F:           b2 = (const float*)d_in[i]; break;
            default: break;
        }
    }
    if (!x)  x  = (const float*)d_in[0];
    if (!ei) ei = d_in[1];
    if (!W1 && n_in > 3) W1 = (const float*)d_in[3];
    if (!b1 && n_in > 4) b1 = (const float*)d_in[4];
    if (!W2 && n_in > 5) W2 = (const float*)d_in[5];
    if (!b2 && n_in > 6) b2 = (const float*)d_in[6];

    float* out = (float*)d_out;

    k_init <<<NBLK + 1, 256>>>(ei);                  // #1
    k_count<<<(N_EDGES + 255) / 256, 256>>>(ei);     // #2
    k_bsum <<<NBLK, 256>>>();                        // #3
    k_scan3<<<NBLK, 256>>>();                        // #4
    k_fill <<<(N_EDGES + 255) / 256, 256>>>(ei);     // #5
    k_gemm1<<<(N_NODES + 127) / 128, 256>>>(x, W1);  // #6 (profiled slot)
    k_prop1g2<<<(N_NODES + 7) / 8, 256>>>(b1, W2);   // #7
    k_prop2  <<<(N_NODES + 7) / 8, 256>>>(b2, out);  // #8
}

// round 11
// speedup vs baseline: 1.1590x; 1.1590x over previous
#include <cuda_runtime.h>

#define N_NODES 100000
#define N_EDGES 1600000
#define IN_F 128
#define HID_F 64
#define CLS_F 32
#define NBLK 391   // ceil(N_NODES/256)

// ---------------- scratch (16B-aligned for vector access) ------------------
__device__ __align__(16) float gv56_xw1[N_NODES * HID_F];  // x @ W1 (unscaled)
__device__ __align__(16) float gv56_hw2s[N_NODES * CLS_F]; // dinv[v]*(h@W2)[v]
__device__ __align__(16) float gv56_dinv[N_NODES];
__device__ int   gv56_cnt[N_NODES];
__device__ int   gv56_rowptr[N_NODES + 1];
__device__ int   gv56_cursor[N_NODES];
__device__ int   gv56_col[N_EDGES];
__device__ int   gv56_bsum[512];
__device__ int   gv56_is64;

// ---------------- init: zero cnt + detect edge dtype ------------------------
__global__ __launch_bounds__(256) void k_init(const void* __restrict__ ei) {
    if (blockIdx.x == NBLK) {
        if (threadIdx.x < 32) {
            const long long* p = (const long long*)ei;
            long long v0 = p[threadIdx.x];
            long long v1 = p[threadIdx.x + 32];
            int bad = (v0 < 0) | (v0 >= (long long)N_NODES) |
                      (v1 < 0) | (v1 >= (long long)N_NODES);
            unsigned m = __ballot_sync(0xffffffffu, bad);
            if (threadIdx.x == 0) gv56_is64 = (m == 0u);
        }
        return;
    }
    int v = blockIdx.x * 256 + threadIdx.x;
    if (v < N_NODES) gv56_cnt[v] = 0;
}

__device__ __forceinline__ int edge_at(const void* __restrict__ ei, long long idx) {
    if (gv56_is64) return (int)((const long long*)ei)[idx];
    return ((const int*)ei)[idx];
}

// ---------------- CSR build --------------------------------------------------
__global__ __launch_bounds__(256) void k_count(const void* __restrict__ ei) {
    int e = blockIdx.x * 256 + threadIdx.x;
    if (e < N_EDGES) {
        int d = edge_at(ei, (long long)N_EDGES + e);
        if ((unsigned)d < (unsigned)N_NODES) atomicAdd(&gv56_cnt[d], 1);
    }
}

__global__ __launch_bounds__(256) void k_bsum() {
    __shared__ int red[8];
    int i = blockIdx.x * 256 + threadIdx.x;
    int v = (i < N_NODES) ? gv56_cnt[i] : 0;
#pragma unroll
    for (int o = 16; o; o >>= 1) v += __shfl_down_sync(0xffffffffu, v, o);
    if ((threadIdx.x & 31) == 0) red[threadIdx.x >> 5] = v;
    __syncthreads();
    if (threadIdx.x < 8) {
        int s = red[threadIdx.x];
#pragma unroll
        for (int o = 4; o; o >>= 1) s += __shfl_down_sync(0xffu, s, o);
        if (threadIdx.x == 0) gv56_bsum[blockIdx.x] = s;
    }
}

__global__ __launch_bounds__(256) void k_scan3() {
    __shared__ int s[256];
    __shared__ int red[8];
    const int t = threadIdx.x;

    int part = 0;
    for (int j = t; j < blockIdx.x; j += 256) part += gv56_bsum[j];
#pragma unroll
    for (int o = 16; o; o >>= 1) part += __shfl_down_sync(0xffffffffu, part, o);
    if ((t & 31) == 0) red[t >> 5] = part;
    __syncthreads();
    if (t < 8) {
        int sr = red[t];
#pragma unroll
        for (int o = 4; o; o >>= 1) sr += __shfl_down_sync(0xffu, sr, o);
        if (t == 0) red[0] = sr;
    }
    __syncthreads();
    const int off = red[0];

    int i = blockIdx.x * 256 + t;
    int v = (i < N_NODES) ? gv56_cnt[i] : 0;
    s[t] = v;
    __syncthreads();
    for (int o = 1; o < 256; o <<= 1) {
        int a = 0;
        if (t >= o) a = s[t - o];
        __syncthreads();
        s[t] += a;
        __syncthreads();
    }
    if (i < N_NODES) {
        int r = off + s[t] - v;
        gv56_rowptr[i] = r;
        gv56_cursor[i] = r;
        gv56_dinv[i] = rsqrtf((float)(v + 1));
        if (i == N_NODES - 1) gv56_rowptr[N_NODES] = r + v;
    }
}

__global__ __launch_bounds__(256) void k_fill(const void* __restrict__ ei) {
    int e = blockIdx.x * 256 + threadIdx.x;
    if (e < N_EDGES) {
        int s = edge_at(ei, e);
        int d = edge_at(ei, (long long)N_EDGES + e);
        if ((unsigned)d < (unsigned)N_NODES && (unsigned)s < (unsigned)N_NODES) {
            int slot = atomicAdd(&gv56_cursor[d], 1);
            gv56_col[slot] = s;
        }
    }
}

// ---------------- GEMM1 (R6 winner): xw1 = X @ W1 ----------------------------
// 64 nodes x 64 cols per block, 256 threads, 4x4 register tile. No deps.
__global__ __launch_bounds__(256) void k_gemm1(const float* __restrict__ X,
                                               const float* __restrict__ W) {
    __shared__ __align__(16) float sW[IN_F * HID_F];   // 32 KB
    __shared__ __align__(16) float sX[64 * 36];        // 9 KB

    const int tid = threadIdx.x;
    const int m0 = blockIdx.x * 64;
    const int ty = tid >> 4;
    const int tx = tid & 15;

    for (int i = tid; i < IN_F * HID_F / 4; i += 256)
        ((float4*)sW)[i] = ((const float4*)W)[i];

    float acc[4][4];
#pragma unroll
    for (int i = 0; i < 4; i++)
#pragma unroll
        for (int j = 0; j < 4; j++) acc[i][j] = 0.0f;

    for (int kt = 0; kt < IN_F; kt += 32) {
        __syncthreads();
        for (int i = tid; i < 64 * 8; i += 256) {
            int r = i >> 3, c4 = i & 7;
            int gr = m0 + r;
            float4 v = make_float4(0.f, 0.f, 0.f, 0.f);
            if (gr < N_NODES)
                v = *(const float4*)&X[(size_t)gr * IN_F + kt + c4 * 4];
            *(float4*)&sX[r * 36 + c4 * 4] = v;
        }
        __syncthreads();

#pragma unroll
        for (int kk = 0; kk < 32; kk++) {
            float4 w4 = ((const float4*)(sW + (kt + kk) * HID_F))[tx];
            float a0 = sX[(ty * 4 + 0) * 36 + kk];
            float a1 = sX[(ty * 4 + 1) * 36 + kk];
            float a2 = sX[(ty * 4 + 2) * 36 + kk];
            float a3 = sX[(ty * 4 + 3) * 36 + kk];
            acc[0][0] = fmaf(a0, w4.x, acc[0][0]);
            acc[0][1] = fmaf(a0, w4.y, acc[0][1]);
            acc[0][2] = fmaf(a0, w4.z, acc[0][2]);
            acc[0][3] = fmaf(a0, w4.w, acc[0][3]);
            acc[1][0] = fmaf(a1, w4.x, acc[1][0]);
            acc[1][1] = fmaf(a1, w4.y, acc[1][1]);
            acc[1][2] = fmaf(a1, w4.z, acc[1][2]);
            acc[1][3] = fmaf(a1, w4.w, acc[1][3]);
            acc[2][0] = fmaf(a2, w4.x, acc[2][0]);
            acc[2][1] = fmaf(a2, w4.y, acc[2][1]);
            acc[2][2] = fmaf(a2, w4.z, acc[2][2]);
            acc[2][3] = fmaf(a2, w4.w, acc[2][3]);
            acc[3][0] = fmaf(a3, w4.x, acc[3][0]);
            acc[3][1] = fmaf(a3, w4.y, acc[3][1]);
            acc[3][2] = fmaf(a3, w4.z, acc[3][2]);
            acc[3][3] = fmaf(a3, w4.w, acc[3][3]);
        }
    }

#pragma unroll
    for (int i = 0; i < 4; i++) {
        int gr = m0 + ty * 4 + i;
        if (gr < N_NODES) {
            float4 o = make_float4(acc[i][0], acc[i][1], acc[i][2], acc[i][3]);
            *(float4*)&gv56_xw1[(size_t)gr * HID_F + tx * 4] = o;
        }
    }
}

// ---------------- fused prop1 + ReLU + GEMM2 (dinv gather) -------------------
// h[v] = relu(dv*(dv*xw[v] + sum_u du*xw[u]) + b1); hw2s[v] = dv*(h@W2)
__global__ __launch_bounds__(256) void k_prop1g2(const float* __restrict__ b1,
                                                 const float* __restrict__ W2) {
    __shared__ __align__(16) float sh[8][HID_F];
    const int warp = threadIdx.x >> 5;
    const int lane = threadIdx.x & 31;
    const int v = blockIdx.x * 8 + warp;
    if (v >= N_NODES) return;

    const float2* __restrict__ xw2 = (const float2*)gv56_xw1;
    float dv = gv56_dinv[v];
    float2 self = xw2[(size_t)v * 32 + lane];
    float ax = dv * self.x;
    float ay = dv * self.y;

    int p = gv56_rowptr[v];
    const int e = gv56_rowptr[v + 1];
    for (; p + 8 <= e; p += 8) {
        int u0 = gv56_col[p],     u1 = gv56_col[p + 1];
        int u2 = gv56_col[p + 2], u3 = gv56_col[p + 3];
        int u4 = gv56_col[p + 4], u5 = gv56_col[p + 5];
        int u6 = gv56_col[p + 6], u7 = gv56_col[p + 7];
        float d0 = gv56_dinv[u0], d1 = gv56_dinv[u1];
        float d2 = gv56_dinv[u2], d3 = gv56_dinv[u3];
        float d4 = gv56_dinv[u4], d5 = gv56_dinv[u5];
        float d6 = gv56_dinv[u6], d7 = gv56_dinv[u7];
        float2 f0 = xw2[(size_t)u0 * 32 + lane];
        float2 f1 = xw2[(size_t)u1 * 32 + lane];
        float2 f2 = xw2[(size_t)u2 * 32 + lane];
        float2 f3 = xw2[(size_t)u3 * 32 + lane];
        float2 f4 = xw2[(size_t)u4 * 32 + lane];
        float2 f5 = xw2[(size_t)u5 * 32 + lane];
        float2 f6 = xw2[(size_t)u6 * 32 + lane];
        float2 f7 = xw2[(size_t)u7 * 32 + lane];
        ax += d0 * f0.x + d1 * f1.x + d2 * f2.x + d3 * f3.x
            + d4 * f4.x + d5 * f5.x + d6 * f6.x + d7 * f7.x;
        ay += d0 * f0.y + d1 * f1.y + d2 * f2.y + d3 * f3.y
            + d4 * f4.y + d5 * f5.y + d6 * f6.y + d7 * f7.y;
    }
    for (; p < e; p++) {
        int u = gv56_col[p];
        float du = gv56_dinv[u];
        float2 f = xw2[(size_t)u * 32 + lane];
        ax += du * f.x;
        ay += du * f.y;
    }

    float2 bb = ((const float2*)b1)[lane];
    sh[warp][2 * lane]     = fmaxf(fmaf(ax, dv, bb.x), 0.0f);
    sh[warp][2 * lane + 1] = fmaxf(fmaf(ay, dv, bb.y), 0.0f);
    __syncwarp();

    float o = 0.0f;
#pragma unroll 8
    for (int k = 0; k < HID_F; k++)
        o = fmaf(sh[warp][k], W2[k * CLS_F + lane], o);
    gv56_hw2s[(size_t)v * CLS_F + lane] = o * dv;   // pre-scaled for prop2
}

// ---------------- prop2: out[v] = dv*(hw2s[v] + sum_u hw2s[u]) + b2 ---------
__global__ __launch_bounds__(256) void k_prop2(const float* __restrict__ b2,
                                               float* __restrict__ out) {
    const int warp = threadIdx.x >> 5;
    const int lane = threadIdx.x & 31;
    const int v = blockIdx.x * 8 + warp;
    if (v >= N_NODES) return;

    float dv = gv56_dinv[v];
    float acc = gv56_hw2s[(size_t)v * CLS_F + lane];

    int p = gv56_rowptr[v];
    const int e = gv56_rowptr[v + 1];
    for (; p + 8 <= e; p += 8) {
        int u0 = gv56_col[p],     u1 = gv56_col[p + 1];
        int u2 = gv56_col[p + 2], u3 = gv56_col[p + 3];
        int u4 = gv56_col[p + 4], u5 = gv56_col[p + 5];
        int u6 = gv56_col[p + 6], u7 = gv56_col[p + 7];
        float f0 = gv56_hw2s[(size_t)u0 * CLS_F + lane];
        float f1 = gv56_hw2s[(size_t)u1 * CLS_F + lane];
        float f2 = gv56_hw2s[(size_t)u2 * CLS_F + lane];
        float f3 = gv56_hw2s[(size_t)u3 * CLS_F + lane];
        float f4 = gv56_hw2s[(size_t)u4 * CLS_F + lane];
        float f5 = gv56_hw2s[(size_t)u5 * CLS_F + lane];
        float f6 = gv56_hw2s[(size_t)u6 * CLS_F + lane];
        float f7 = gv56_hw2s[(size_t)u7 * CLS_F + lane];
        acc += f0 + f1 + f2 + f3 + f4 + f5 + f6 + f7;
    }
    for (; p < e; p++) {
        int u = gv56_col[p];
        acc += gv56_hw2s[(size_t)u * CLS_F + lane];
    }
    out[(size_t)v * CLS_F + lane] = fmaf(acc, dv, b2[lane]);
}

// ---------------- launch: fork gemm1 onto side stream ------------------------
extern "C" void kernel_launch(void* const* d_in, const int* in_sizes, int n_in,
                              void* d_out, int out_size) {
    static cudaStream_t s2 = nullptr;
    static cudaEvent_t evFork = nullptr, evGemm = nullptr;
    if (s2 == nullptr) {
        cudaStreamCreateWithFlags(&s2, cudaStreamNonBlocking);
        cudaEventCreateWithFlags(&evFork, cudaEventDisableTiming);
        cudaEventCreateWithFlags(&evGemm, cudaEventDisableTiming);
    }

    const float* x  = nullptr;
    const void*  ei = nullptr;
    const float* W1 = nullptr;
    const float* b1 = nullptr;
    const float* W2 = nullptr;
    const float* b2 = nullptr;

    for (int i = 0; i < n_in; i++) {
        switch (in_sizes[i]) {
            case N_NODES * IN_F:  x  = (const float*)d_in[i]; break;
            case 2 * N_EDGES:     ei = d_in[i];               break;
            case N_EDGES:         /* edge_attr unused */       break;
            case IN_F * HID_F:    W1 = (const float*)d_in[i]; break;
            case HID_F:           b1 = (const float*)d_in[i]; break;
            case HID_F * CLS_F:   W2 = (const float*)d_in[i]; break;
            case CLS_F:           b2 = (const float*)d_in[i]; break;
            default: break;
        }
    }
    if (!x)  x  = (const float*)d_in[0];
    if (!ei) ei = d_in[1];
    if (!W1 && n_in > 3) W1 = (const float*)d_in[3];
    if (!b1 && n_in > 4) b1 = (const float*)d_in[4];
    if (!W2 && n_in > 5) W2 = (const float*)d_in[5];
    if (!b2 && n_in > 6) b2 = (const float*)d_in[6];

    float* out = (float*)d_out;

    // fork: gemm1 runs concurrently with the CSR build chain
    cudaEventRecord(evFork, 0);
    cudaStreamWaitEvent(s2, evFork, 0);
    k_gemm1<<<(N_NODES + 63) / 64, 256, 0, s2>>>(x, W1);
    cudaEventRecord(evGemm, s2);

    // CSR chain on the main stream
    k_init <<<NBLK + 1, 256>>>(ei);
    k_count<<<(N_EDGES + 255) / 256, 256>>>(ei);
    k_bsum <<<NBLK, 256>>>();
    k_scan3<<<NBLK, 256>>>();
    k_fill <<<(N_EDGES + 255) / 256, 256>>>(ei);

    // join, then fused prop layers
    cudaStreamWaitEvent(0, evGemm, 0);
    k_prop1g2<<<(N_NODES + 7) / 8, 256>>>(b1, W2);
    k_prop2  <<<(N_NODES + 7) / 8, 256>>>(b2, out);
}